// round 2
// baseline (speedup 1.0000x reference)
#include <cuda_runtime.h>
#include <math.h>

// Problem constants (fixed shapes for GAT_79894981640316)
#define NMAX   100000
#define EMAX   1600000
#define F      128
#define NHEADS 4
#define HID    32
#define NCLS   349
#define NLAYER 2

// ---------------- scratch (device globals; no allocation allowed) ----------
__device__ float  g_xs[NMAX * F];
__device__ float  g_xd[NMAX * F];
__device__ float  g_h [NMAX * F];      // conv accumulator (init = lin proj + biases)
__device__ float  g_x1[NMAX * F];      // layer-0 output
__device__ float  g_x2[NMAX * F];      // layer-1 output
__device__ float  g_ssrc [NMAX * NHEADS];
__device__ float  g_sdst [NMAX * NHEADS];
__device__ float  g_m    [NMAX * NHEADS];
__device__ float  g_denom[NMAX * NHEADS];
__device__ float  g_p    [EMAX * NHEADS];
__device__ double g_bnsum[F];
__device__ double g_bnsq [F];

// ---------------- float atomicMax ------------------------------------------
__device__ __forceinline__ void atomicMaxFloat(float* addr, float value) {
    if (value >= 0.0f) {
        atomicMax((int*)addr, __float_as_int(value));
    } else {
        atomicMin((unsigned int*)addr, __float_as_uint(value));
    }
}

// ---------------- SGEMM: C[M,N] = A[M,K] * B[K,N] (+bias1 +bias2) ----------
#define BM 64
#define BN 64
#define BK 16
#define TM 4
#define TN 4
__global__ void sgemm_kernel(const float* __restrict__ A,
                             const float* __restrict__ B,
                             const float* __restrict__ bias1,
                             const float* __restrict__ bias2,
                             float* __restrict__ C,
                             int M, int N, int K)
{
    __shared__ float As[BK][BM];
    __shared__ float Bs[BK][BN];

    const int block_row = blockIdx.y * BM;
    const int block_col = blockIdx.x * BN;
    const int tid = threadIdx.x;          // 0..255
    const int tr  = tid >> 4;             // 0..15
    const int tc  = tid & 15;             // 0..15

    float acc[TM][TN];
#pragma unroll
    for (int i = 0; i < TM; i++)
#pragma unroll
        for (int j = 0; j < TN; j++) acc[i][j] = 0.0f;

    for (int k0 = 0; k0 < K; k0 += BK) {
        // A tile (BM x BK), stored transposed As[k][m]
#pragma unroll
        for (int i = tid; i < BM * BK; i += 256) {
            int m = i / BK, k = i % BK;
            int gm = block_row + m;
            As[k][m] = (gm < M) ? A[(long long)gm * K + k0 + k] : 0.0f;
        }
        // B tile (BK x BN)
#pragma unroll
        for (int i = tid; i < BK * BN; i += 256) {
            int k = i / BN, n = i % BN;
            int gn = block_col + n;
            Bs[k][n] = (gn < N) ? B[(long long)(k0 + k) * N + gn] : 0.0f;
        }
        __syncthreads();

#pragma unroll
        for (int k = 0; k < BK; k++) {
            float a[TM], b[TN];
#pragma unroll
            for (int i = 0; i < TM; i++) a[i] = As[k][tr * TM + i];
#pragma unroll
            for (int j = 0; j < TN; j++) b[j] = Bs[k][tc * TN + j];
#pragma unroll
            for (int i = 0; i < TM; i++)
#pragma unroll
                for (int j = 0; j < TN; j++) acc[i][j] += a[i] * b[j];
        }
        __syncthreads();
    }

#pragma unroll
    for (int i = 0; i < TM; i++) {
        int gm = block_row + tr * TM + i;
        if (gm >= M) continue;
#pragma unroll
        for (int j = 0; j < TN; j++) {
            int gn = block_col + tc * TN + j;
            if (gn >= N) continue;
            float v = acc[i][j];
            if (bias1) v += bias1[gn];
            if (bias2) v += bias2[gn];
            C[(long long)gm * N + gn] = v;
        }
    }
}

// ---------------- per-node prep: attention scores + init m/denom/bn --------
__global__ void node_prep_kernel(const float* __restrict__ asrc,
                                 const float* __restrict__ adst,
                                 int N)
{
    int idx = blockIdx.x * blockDim.x + threadIdx.x;
    if (idx < F) { g_bnsum[idx] = 0.0; g_bnsq[idx] = 0.0; }
    if (idx >= N * NHEADS) return;
    int n = idx >> 2;
    int h = idx & 3;
    const float* xsr = g_xs + (long long)n * F + h * HID;
    const float* xdr = g_xd + (long long)n * F + h * HID;
    float ss = 0.0f, sd = 0.0f;
#pragma unroll
    for (int c = 0; c < HID; c++) {
        ss += xsr[c] * asrc[h * HID + c];
        sd += xdr[c] * adst[h * HID + c];
    }
    g_ssrc[idx]  = ss;
    g_sdst[idx]  = sd;
    g_m[idx]     = __int_as_float(0xff800000);  // -inf
    g_denom[idx] = 0.0f;
}

// ---------------- edge pass 1: segment max of leaky_relu scores ------------
__global__ void edge_max_kernel(const int* __restrict__ ei, int E)
{
    int idx = blockIdx.x * blockDim.x + threadIdx.x;
    if (idx >= E * NHEADS) return;
    int e = idx >> 2;
    int h = idx & 3;
    int s = ei[e];
    int d = ei[E + e];
    float v = g_ssrc[s * NHEADS + h] + g_sdst[d * NHEADS + h];
    v = (v >= 0.0f) ? v : 0.2f * v;          // leaky_relu(0.2)
    atomicMaxFloat(&g_m[d * NHEADS + h], v);
}

// ---------------- edge pass 2: p = exp(e - m[dst]); denom += p -------------
__global__ void edge_p_kernel(const int* __restrict__ ei, int E)
{
    int idx = blockIdx.x * blockDim.x + threadIdx.x;
    if (idx >= E * NHEADS) return;
    int e = idx >> 2;
    int h = idx & 3;
    int s = ei[e];
    int d = ei[E + e];
    float v = g_ssrc[s * NHEADS + h] + g_sdst[d * NHEADS + h];
    v = (v >= 0.0f) ? v : 0.2f * v;
    float p = expf(v - g_m[d * NHEADS + h]);
    g_p[idx] = p;
    atomicAdd(&g_denom[d * NHEADS + h], p);
}

// ---------------- edge pass 3: scatter messages into g_h -------------------
__global__ void edge_msg_kernel(const int* __restrict__ ei, int E)
{
    int idx = blockIdx.x * blockDim.x + threadIdx.x;
    if (idx >= E * F) return;        // E*F = 204.8M < 2^31
    int e = idx >> 7;
    int c = idx & 127;
    int h = c >> 5;
    int s = ei[e];
    int d = ei[E + e];
    float alpha = g_p[e * NHEADS + h] / (g_denom[d * NHEADS + h] + 1e-16f);
    atomicAdd(&g_h[(long long)d * F + c], g_xs[(long long)s * F + c] * alpha);
}

// ---------------- batch-norm reduction (fp64 accumulation) -----------------
__global__ void bn_reduce_kernel(int N)
{
    int c  = threadIdx.x;                   // 128 threads = 128 features
    int r0 = blockIdx.x * 256;
    int r1 = min(r0 + 256, N);
    double s = 0.0, q = 0.0;
    for (int r = r0; r < r1; r++) {
        float v = g_h[(long long)r * F + c];
        s += (double)v;
        q += (double)v * (double)v;
    }
    atomicAdd(&g_bnsum[c], s);
    atomicAdd(&g_bnsq[c],  q);
}

// ---------------- batch-norm apply + relu ----------------------------------
__global__ void bn_apply_kernel(const float* __restrict__ gamma,
                                const float* __restrict__ beta,
                                float* __restrict__ xout,
                                int N)
{
    int idx = blockIdx.x * blockDim.x + threadIdx.x;
    if (idx >= N * F) return;
    int c = idx & 127;
    double mu = g_bnsum[c] / (double)N;
    double var = g_bnsq[c] / (double)N - mu * mu;
    float mean  = (float)mu;
    float scale = gamma[c] * rsqrtf((float)var + 1e-5f);
    float v = scale * (g_h[idx] - mean) + beta[c];
    xout[idx] = (v > 0.0f) ? v : 0.0f;
}

// ---------------- host-side launcher ----------------------------------------
extern "C" void kernel_launch(void* const* d_in, const int* in_sizes, int n_in,
                              void* d_out, int out_size)
{
    const float* x     = (const float*)d_in[0];
    const int*   ei    = (const int*)  d_in[1];
    const float* Wsrc  = (const float*)d_in[2];
    const float* Wdst  = (const float*)d_in[3];
    const float* asrc  = (const float*)d_in[4];
    const float* adst  = (const float*)d_in[5];
    const float* cbias = (const float*)d_in[6];
    const float* linW  = (const float*)d_in[7];
    const float* linb  = (const float*)d_in[8];
    const float* gamma = (const float*)d_in[9];
    const float* beta  = (const float*)d_in[10];
    const float* fcW   = (const float*)d_in[11];
    const float* fcb   = (const float*)d_in[12];
    float* out = (float*)d_out;

    const int N = in_sizes[0] / F;
    const int E = in_sizes[1] / 2;

    // resolve scratch symbol addresses (host API, capture-safe)
    static float* xs_p = nullptr;
    static float* xd_p = nullptr;
    static float* h_p  = nullptr;
    static float* x1_p = nullptr;
    static float* x2_p = nullptr;
    if (!xs_p) {
        cudaGetSymbolAddress((void**)&xs_p, g_xs);
        cudaGetSymbolAddress((void**)&xd_p, g_xd);
        cudaGetSymbolAddress((void**)&h_p,  g_h);
        cudaGetSymbolAddress((void**)&x1_p, g_x1);
        cudaGetSymbolAddress((void**)&x2_p, g_x2);
    }

    dim3 gemm_grid_proj((F + BN - 1) / BN, (N + BM - 1) / BM);   // 2 x 1563
    dim3 gemm_grid_fc  ((NCLS + BN - 1) / BN, (N + BM - 1) / BM);

    const int eh_blocks  = (E * NHEADS + 255) / 256;
    const int nh_blocks  = (N * NHEADS + 255) / 256;
    const int msg_blocks = (E * F / 256) + 1;
    const int nf_blocks  = (N * F + 255) / 256;
    const int bnr_blocks = (N + 255) / 256;

    const float* xin = x;
    for (int i = 0; i < NLAYER; i++) {
        const float* Ws = Wsrc + (long long)i * F * F;
        const float* Wd = Wdst + (long long)i * F * F;
        const float* Wl = linW + (long long)i * F * F;

        sgemm_kernel<<<gemm_grid_proj, 256>>>(xin, Ws, nullptr, nullptr, xs_p, N, F, F);
        sgemm_kernel<<<gemm_grid_proj, 256>>>(xin, Wd, nullptr, nullptr, xd_p, N, F, F);
        // g_h = x @ lin_W + lin_b + conv_bias  (conv messages accumulate on top)
        sgemm_kernel<<<gemm_grid_proj, 256>>>(xin, Wl, linb + i * F, cbias + i * F,
                                              h_p, N, F, F);

        node_prep_kernel<<<nh_blocks, 256>>>(asrc + i * NHEADS * HID,
                                             adst + i * NHEADS * HID, N);
        edge_max_kernel<<<eh_blocks, 256>>>(ei, E);
        edge_p_kernel  <<<eh_blocks, 256>>>(ei, E);
        edge_msg_kernel<<<msg_blocks, 256>>>(ei, E);

        bn_reduce_kernel<<<bnr_blocks, 128>>>(N);
        float* xo = (i == 0) ? x1_p : x2_p;
        bn_apply_kernel<<<nf_blocks, 256>>>(gamma + i * F, beta + i * F, xo, N);
        xin = xo;
    }

    // final classifier
    sgemm_kernel<<<gemm_grid_fc, 256>>>(xin, fcW, fcb, nullptr, out, N, NCLS, F);
}

// round 3
// speedup vs baseline: 2.3579x; 2.3579x over previous
#include <cuda_runtime.h>
#include <math.h>

#define NMAX   100000
#define EMAX   1600000
#define F      128
#define NHEADS 4
#define HID    32
#define NCLS   349
#define NLAYER 2
#define BNB    ((NMAX + 255) / 256)   // 391 bn partial blocks

// ---------------- scratch (device globals; no allocation allowed) ----------
__device__ float  g_xs[NMAX * F];
__device__ float  g_xd[NMAX * F];
__device__ float  g_h [NMAX * F];
__device__ float  g_x1[NMAX * F];
__device__ float  g_x2[NMAX * F];
__device__ float  g_ssrc [NMAX * NHEADS];
__device__ float  g_sdst [NMAX * NHEADS];
__device__ float  g_m    [NMAX * NHEADS];
__device__ float  g_denom[NMAX * NHEADS];
__device__ float  g_p    [EMAX * NHEADS];
__device__ double g_bnpS[BNB * F];
__device__ double g_bnpQ[BNB * F];
__device__ float  g_bnscale[F];
__device__ float  g_bnbias [F];

// ---------------- float atomicMax ------------------------------------------
__device__ __forceinline__ void atomicMaxFloat(float* addr, float value) {
    if (value >= 0.0f) {
        atomicMax((int*)addr, __float_as_int(value));
    } else {
        atomicMin((unsigned int*)addr, __float_as_uint(value));
    }
}

// ---------------- SGEMM: 128x128 block, 8x8 per thread, 256 threads --------
#define GBM 128
#define GBN 128
#define GBK 16
__global__ __launch_bounds__(256)
void sgemm128(const float* __restrict__ A,
              const float* __restrict__ B,
              const float* __restrict__ bias1,
              const float* __restrict__ bias2,
              float* __restrict__ C,
              int M, int N, int K)
{
    __shared__ float As[GBK][GBM + 4];
    __shared__ float Bs[GBK][GBN];

    const int tid  = threadIdx.x;
    const int tr   = tid >> 4;          // 0..15 (row group)
    const int tc   = tid & 15;          // 0..15 (col group)
    const int row0 = blockIdx.y * GBM;
    const int col0 = blockIdx.x * GBN;

    float acc[8][8];
#pragma unroll
    for (int i = 0; i < 8; i++)
#pragma unroll
        for (int j = 0; j < 8; j++) acc[i][j] = 0.0f;

    for (int k0 = 0; k0 < K; k0 += GBK) {
        // A tile: 128 rows x 16 cols, float4 loads, stored transposed
#pragma unroll
        for (int it = 0; it < 2; it++) {
            int i  = tid + it * 256;    // 0..511 float4 slots
            int m  = i >> 2;
            int kq = (i & 3) << 2;
            float4 v = make_float4(0.f, 0.f, 0.f, 0.f);
            int gm = row0 + m;
            if (gm < M) v = *(const float4*)(A + (size_t)gm * K + k0 + kq);
            As[kq + 0][m] = v.x;
            As[kq + 1][m] = v.y;
            As[kq + 2][m] = v.z;
            As[kq + 3][m] = v.w;
        }
        // B tile: 16 rows x 128 cols, scalar (N may not be mult of 4)
#pragma unroll
        for (int i = tid; i < GBK * GBN; i += 256) {
            int kk = i >> 7;
            int nn = i & 127;
            int gn = col0 + nn;
            Bs[kk][nn] = (gn < N) ? B[(size_t)(k0 + kk) * N + gn] : 0.0f;
        }
        __syncthreads();

#pragma unroll
        for (int k = 0; k < GBK; k++) {
            float a[8], b[8];
            *(float4*)&a[0] = *(const float4*)&As[k][tr * 8];
            *(float4*)&a[4] = *(const float4*)&As[k][tr * 8 + 4];
            *(float4*)&b[0] = *(const float4*)&Bs[k][tc * 8];
            *(float4*)&b[4] = *(const float4*)&Bs[k][tc * 8 + 4];
#pragma unroll
            for (int i = 0; i < 8; i++)
#pragma unroll
                for (int j = 0; j < 8; j++)
                    acc[i][j] += a[i] * b[j];
        }
        __syncthreads();
    }

#pragma unroll
    for (int i = 0; i < 8; i++) {
        int gm = row0 + tr * 8 + i;
        if (gm >= M) continue;
#pragma unroll
        for (int j = 0; j < 8; j++) {
            int gn = col0 + tc * 8 + j;
            if (gn >= N) continue;
            float v = acc[i][j];
            if (bias1) v += bias1[gn];
            if (bias2) v += bias2[gn];
            C[(size_t)gm * N + gn] = v;
        }
    }
}

// ---------------- node prep: warp per node, coalesced float4 ---------------
__global__ void node_prep_kernel(const float* __restrict__ asrc,
                                 const float* __restrict__ adst,
                                 int N)
{
    __shared__ float sa[F], sd_[F];
    int tid = threadIdx.x;
    if (tid < F) { sa[tid] = asrc[tid]; sd_[tid] = adst[tid]; }
    __syncthreads();

    int warp = (blockIdx.x * blockDim.x + tid) >> 5;
    int lane = tid & 31;
    if (warp >= N) return;

    float4 vs = *(const float4*)(g_xs + (size_t)warp * F + lane * 4);
    float4 vd = *(const float4*)(g_xd + (size_t)warp * F + lane * 4);
    float4 as4 = *(const float4*)&sa[lane * 4];
    float4 ad4 = *(const float4*)&sd_[lane * 4];

    float ss = vs.x * as4.x + vs.y * as4.y + vs.z * as4.z + vs.w * as4.w;
    float sd = vd.x * ad4.x + vd.y * ad4.y + vd.z * ad4.z + vd.w * ad4.w;

#pragma unroll
    for (int o = 4; o >= 1; o >>= 1) {
        ss += __shfl_down_sync(0xffffffffu, ss, o, 8);
        sd += __shfl_down_sync(0xffffffffu, sd, o, 8);
    }
    if ((lane & 7) == 0) {
        int h = lane >> 3;
        int idx = warp * NHEADS + h;
        g_ssrc[idx]  = ss;
        g_sdst[idx]  = sd;
        g_m[idx]     = __int_as_float(0xff800000);   // -inf
        g_denom[idx] = 0.0f;
    }
}

// ---------------- edge pass 1: segment max ---------------------------------
__global__ void edge_max_kernel(const int* __restrict__ ei, int E)
{
    int idx = blockIdx.x * blockDim.x + threadIdx.x;
    if (idx >= E * NHEADS) return;
    int e = idx >> 2;
    int h = idx & 3;
    int s = ei[e];
    int d = ei[E + e];
    float v = g_ssrc[s * NHEADS + h] + g_sdst[d * NHEADS + h];
    v = (v >= 0.0f) ? v : 0.2f * v;
    atomicMaxFloat(&g_m[d * NHEADS + h], v);
}

// ---------------- edge pass 2: p = exp(e-m); denom += p --------------------
__global__ void edge_p_kernel(const int* __restrict__ ei, int E)
{
    int idx = blockIdx.x * blockDim.x + threadIdx.x;
    if (idx >= E * NHEADS) return;
    int e = idx >> 2;
    int h = idx & 3;
    int s = ei[e];
    int d = ei[E + e];
    float v = g_ssrc[s * NHEADS + h] + g_sdst[d * NHEADS + h];
    v = (v >= 0.0f) ? v : 0.2f * v;
    float p = expf(v - g_m[d * NHEADS + h]);
    g_p[idx] = p;
    atomicAdd(&g_denom[d * NHEADS + h], p);
}

// ---------------- edge pass 3: warp per edge, vectorized reduction ---------
__global__ void edge_msg_kernel(const int* __restrict__ ei, int E)
{
    int warp = (blockIdx.x * blockDim.x + threadIdx.x) >> 5;
    int lane = threadIdx.x & 31;
    if (warp >= E) return;
    int s = ei[warp];
    int d = ei[E + warp];
    int h = lane >> 3;                       // 8 lanes per head
    float alpha = g_p[warp * NHEADS + h] /
                  (g_denom[d * NHEADS + h] + 1e-16f);
    float4 v = *(const float4*)(g_xs + (size_t)s * F + lane * 4);
    v.x *= alpha; v.y *= alpha; v.z *= alpha; v.w *= alpha;
    float* dst = g_h + (size_t)d * F + lane * 4;
    asm volatile("red.global.add.v4.f32 [%0], {%1, %2, %3, %4};"
                 :: "l"(dst), "f"(v.x), "f"(v.y), "f"(v.z), "f"(v.w)
                 : "memory");
}

// ---------------- BN: per-block partials (no global atomics) ---------------
__global__ void bn_reduce_kernel(int N)
{
    int c  = threadIdx.x;                   // 128 threads = channels
    int b  = blockIdx.x;
    int r0 = b * 256;
    int r1 = min(r0 + 256, N);
    double s = 0.0, q = 0.0;
    for (int r = r0; r < r1; r++) {
        float v = g_h[(size_t)r * F + c];
        s += (double)v;
        q += (double)v * (double)v;
    }
    g_bnpS[b * F + c] = s;
    g_bnpQ[b * F + c] = q;
}

__global__ void bn_finalize_kernel(const float* __restrict__ gamma,
                                   const float* __restrict__ beta,
                                   int N, int nblocks)
{
    int c = threadIdx.x;
    double s = 0.0, q = 0.0;
    for (int b = 0; b < nblocks; b++) {
        s += g_bnpS[b * F + c];
        q += g_bnpQ[b * F + c];
    }
    double mu  = s / (double)N;
    double var = q / (double)N - mu * mu;
    float scale = gamma[c] * rsqrtf((float)var + 1e-5f);
    g_bnscale[c] = scale;
    g_bnbias[c]  = beta[c] - scale * (float)mu;
}

__global__ void bn_apply_kernel(float* __restrict__ xout, int N)
{
    int idx = blockIdx.x * blockDim.x + threadIdx.x;
    if (idx >= N * F) return;
    int c = idx & 127;
    float v = g_bnscale[c] * g_h[idx] + g_bnbias[c];
    xout[idx] = (v > 0.0f) ? v : 0.0f;
}

// ---------------- host-side launcher ----------------------------------------
extern "C" void kernel_launch(void* const* d_in, const int* in_sizes, int n_in,
                              void* d_out, int out_size)
{
    const float* x     = (const float*)d_in[0];
    const int*   ei    = (const int*)  d_in[1];
    const float* Wsrc  = (const float*)d_in[2];
    const float* Wdst  = (const float*)d_in[3];
    const float* asrc  = (const float*)d_in[4];
    const float* adst  = (const float*)d_in[5];
    const float* cbias = (const float*)d_in[6];
    const float* linW  = (const float*)d_in[7];
    const float* linb  = (const float*)d_in[8];
    const float* gamma = (const float*)d_in[9];
    const float* beta  = (const float*)d_in[10];
    const float* fcW   = (const float*)d_in[11];
    const float* fcb   = (const float*)d_in[12];
    float* out = (float*)d_out;

    const int N = in_sizes[0] / F;
    const int E = in_sizes[1] / 2;

    static float* xs_p = nullptr;
    static float* xd_p = nullptr;
    static float* h_p  = nullptr;
    static float* x1_p = nullptr;
    static float* x2_p = nullptr;
    if (!xs_p) {
        cudaGetSymbolAddress((void**)&xs_p, g_xs);
        cudaGetSymbolAddress((void**)&xd_p, g_xd);
        cudaGetSymbolAddress((void**)&h_p,  g_h);
        cudaGetSymbolAddress((void**)&x1_p, g_x1);
        cudaGetSymbolAddress((void**)&x2_p, g_x2);
    }

    dim3 gproj(1, (N + GBM - 1) / GBM);                 // 1 x 782
    dim3 gfc((NCLS + GBN - 1) / GBN, (N + GBM - 1) / GBM);

    const int np_blocks  = (N * 32 + 255) / 256;        // warp per node
    const int eh_blocks  = (E * NHEADS + 255) / 256;
    const int msg_blocks = (E * 32 + 255) / 256;        // warp per edge
    const int nf_blocks  = (N * F + 255) / 256;
    const int bnr_blocks = (N + 255) / 256;

    const float* xin = x;
    for (int i = 0; i < NLAYER; i++) {
        const float* Ws = Wsrc + (size_t)i * F * F;
        const float* Wd = Wdst + (size_t)i * F * F;
        const float* Wl = linW + (size_t)i * F * F;

        sgemm128<<<gproj, 256>>>(xin, Ws, nullptr, nullptr, xs_p, N, F, F);
        sgemm128<<<gproj, 256>>>(xin, Wd, nullptr, nullptr, xd_p, N, F, F);
        sgemm128<<<gproj, 256>>>(xin, Wl, linb + i * F, cbias + i * F,
                                 h_p, N, F, F);

        node_prep_kernel<<<np_blocks, 256>>>(asrc + i * NHEADS * HID,
                                             adst + i * NHEADS * HID, N);
        edge_max_kernel<<<eh_blocks, 256>>>(ei, E);
        edge_p_kernel  <<<eh_blocks, 256>>>(ei, E);
        edge_msg_kernel<<<msg_blocks, 256>>>(ei, E);

        bn_reduce_kernel  <<<bnr_blocks, 128>>>(N);
        bn_finalize_kernel<<<1, 128>>>(gamma + i * F, beta + i * F, N, bnr_blocks);
        float* xo = (i == 0) ? x1_p : x2_p;
        bn_apply_kernel<<<nf_blocks, 256>>>(xo, N);
        xin = xo;
    }

    sgemm128<<<gfc, 256>>>(xin, fcW, fcb, nullptr, out, N, NCLS, F);
}